// round 12
// baseline (speedup 1.0000x reference)
#include <cuda_runtime.h>
#include <cuda_bf16.h>
#include <cstdint>
#include <math.h>

#define NBATCH 128
#define CIN    2048
#define COUT   256
#define KNODES 16
#define SPOS   256
#define DOUT   512
#define KFC    4096
#define MROWS  2048
#define KSPLIT 4
#define FUSED_BLOCKS 256
#define FC_KSPLIT 32

// ---------------- device scratch ----------------
__device__ float g_lnorm[NBATCH * KNODES * KNODES];
__device__ __nv_bfloat16 g_whi[COUT * CIN];
__device__ __nv_bfloat16 g_wlo[COUT * CIN];
__device__ __nv_bfloat16 g_fwhi[DOUT * KFC];
__device__ __nv_bfloat16 g_fwlo[DOUT * KFC];
__device__ __nv_bfloat16 g_ahi[MROWS * CIN];
__device__ __nv_bfloat16 g_alo[MROWS * CIN];
__device__ __nv_bfloat16 g_yhi[NBATCH * KFC];
__device__ __nv_bfloat16 g_ylo[NBATCH * KFC];
__device__ float g_xpart[KSPLIT][MROWS * COUT];
__device__ float g_part2[FC_KSPLIT][NBATCH * DOUT];
__device__ volatile int g_bar[4];

// ---------------- async copy helpers ----------------
__device__ __forceinline__ void cp16(void* smem, const void* gmem) {
    unsigned int s = (unsigned int)__cvta_generic_to_shared(smem);
    asm volatile("cp.async.cg.shared.global [%0], [%1], 16;\n" :: "r"(s), "l"(gmem));
}
__device__ __forceinline__ void cp_commit() {
    asm volatile("cp.async.commit_group;\n" ::: "memory");
}
template <int N>
__device__ __forceinline__ void cp_wait() {
    asm volatile("cp.async.wait_group %0;\n" :: "n"(N) : "memory");
}

// ---------------- mma helpers ----------------
__device__ __forceinline__ void mma_bf16(float* c, const unsigned* a, const unsigned* b) {
    asm volatile(
        "mma.sync.aligned.m16n8k16.row.col.f32.bf16.bf16.f32 "
        "{%0,%1,%2,%3},{%4,%5,%6,%7},{%8,%9},{%0,%1,%2,%3};\n"
        : "+f"(c[0]), "+f"(c[1]), "+f"(c[2]), "+f"(c[3])
        : "r"(a[0]), "r"(a[1]), "r"(a[2]), "r"(a[3]), "r"(b[0]), "r"(b[1]));
}
__device__ __forceinline__ void ldsm_x4(unsigned* r, const void* p) {
    unsigned a = (unsigned)__cvta_generic_to_shared(p);
    asm volatile("ldmatrix.sync.aligned.m8n8.x4.shared.b16 {%0,%1,%2,%3}, [%4];\n"
                 : "=r"(r[0]), "=r"(r[1]), "=r"(r[2]), "=r"(r[3]) : "r"(a));
}

// ---------------- grid barrier ----------------
__device__ __forceinline__ void gbar(int id) {
    __syncthreads();
    __threadfence();
    if (threadIdx.x == 0) {
        atomicAdd((int*)&g_bar[id], 1);
        while (g_bar[id] < FUSED_BLOCKS) __nanosleep(64);
    }
    __syncthreads();
}

// ---------------- shared GEMM tile geometry ----------------
#define KT     32
#define APITCH 40
#define BPITCH 40
#define SMB_OFF 0
#define SMA_OFF (2 * 2 * 128 * BPITCH * 2)           // 40960
#define SMEMSZ  (SMA_OFF + 2 * 2 * 64 * APITCH * 2)  // 61440

// ---------------- K12: conv_w split + channel-sum + topk + lnorm + gather ----------------
// grid 128 (one block per n), 1024 threads.
__global__ void __launch_bounds__(1024, 1)
k12_fused(const float* __restrict__ sounds, const float* __restrict__ conv_w) {
    __shared__ float part[4][SPOS];
    __shared__ float feat[SPOS];
    __shared__ int   sel[KNODES];
    __shared__ int   rr[KNODES], cc[KNODES];
    __shared__ float Amat[KNODES][KNODES];
    __shared__ float dinv[KNODES];
    __shared__ int   spos[KNODES];
    __shared__ __nv_bfloat162 smh[2][64][17];
    __shared__ __nv_bfloat162 sml[2][64][17];

    const int n = blockIdx.x;
    const int tid = threadIdx.x;
    const float* snd_n = sounds + (size_t)n * CIN * SPOS;

    // ---- phase 0: barrier reset + conv_w hi/lo split ----
    if (n == 0 && tid < 4) g_bar[tid] = 0;
    {
        int i = (n * 1024 + tid) * 4;
        float4 w4 = *(const float4*)&conv_w[i];
        float w[4] = {w4.x, w4.y, w4.z, w4.w};
#pragma unroll
        for (int j = 0; j < 4; j++) {
            __nv_bfloat16 h = __float2bfloat16_rn(w[j]);
            g_whi[i + j] = h;
            g_wlo[i + j] = __float2bfloat16_rn(w[j] - __bfloat162float(h));
        }
    }

    // ---- phase A: channel sum ----
    {
        const int pos = tid & 255, cg = tid >> 8;
        const float* base = snd_n + (size_t)(cg * 512) * SPOS + pos;
        float a[8];
#pragma unroll
        for (int i = 0; i < 8; i++) a[i] = 0.f;
#pragma unroll 2
        for (int c = 0; c < 512; c += 8) {
#pragma unroll
            for (int i = 0; i < 8; i++) a[i] += base[(c + i) * SPOS];
        }
        part[cg][pos] =
            ((a[0] + a[1]) + (a[2] + a[3])) + ((a[4] + a[5]) + (a[6] + a[7]));
    }
    __syncthreads();
    if (tid < 256)
        feat[tid] = part[0][tid] + part[1][tid] + part[2][tid] + part[3][tid];
    __syncthreads();

    // ---- phase B: top-16 via single-warp register reduction ----
    if (tid < 32) {
        float vals[8];
#pragma unroll
        for (int j = 0; j < 8; j++) vals[j] = feat[tid * 8 + j];
#pragma unroll 1
        for (int it = 0; it < KNODES; it++) {
            unsigned long long k = 0ull;
#pragma unroll
            for (int j = 0; j < 8; j++) {
                unsigned fb = __float_as_uint(vals[j]);
                fb = (fb & 0x80000000u) ? ~fb : (fb | 0x80000000u);
                unsigned long long key =
                    ((unsigned long long)fb << 32) | (unsigned)(255 - (tid * 8 + j));
                if (key > k) k = key;
            }
#pragma unroll
            for (int s = 16; s > 0; s >>= 1) {
                unsigned long long o = __shfl_down_sync(0xffffffffu, k, s);
                if (o > k) k = o;
            }
            k = __shfl_sync(0xffffffffu, k, 0);
            int idx = 255 - (int)(k & 0xffffffffu);
            if (tid == (idx >> 3)) {
                int m = idx & 7;
#pragma unroll
                for (int j = 0; j < 8; j++)
                    if (j == m) vals[j] = -3.4e38f;
            }
            if (tid == 0) sel[it] = idx;
        }
    }
    __syncthreads();

    // ---- phase C: positions + lnorm ----
    if (tid < KNODES) {
        int p = sel[tid];
        int r = (p < 16) ? 0 : ((p >> 4) - 1);
        int q = p & 15;
        int c = (q == 0) ? 15 : (q - 1);
        rr[tid] = r;
        cc[tid] = c;
        spos[tid] = r * 16 + c;
    }
    __syncthreads();
    if (tid < 256) {
        int i = tid >> 4, j = tid & 15;
        float dr = (float)(rr[i] - rr[j]);
        float dc = (float)(cc[i] - cc[j]);
        Amat[i][j] = expf(-(dr * dr + dc * dc) / (2.0f * (float)KNODES));
    }
    __syncthreads();
    if (tid < KNODES) {
        float s = 0.f;
#pragma unroll
        for (int j = 0; j < KNODES; j++) s += Amat[tid][j];
        dinv[tid] = 1.0f / sqrtf(s);
    }
    __syncthreads();
    if (tid < 256) {
        int i = tid >> 4, j = tid & 15;
        g_lnorm[n * 256 + tid] = Amat[i][j] * dinv[i] * dinv[j];
    }

    // ---- phase D: gather + bf16 split + transpose (prefetch depth 2) ----
    {
        const int k = tid & 15, ci = (tid >> 4) & 63;
        const int k2 = tid >> 6, c2 = tid & 63;
        const float* base = snd_n + spos[k];
        __nv_bfloat162* ahi2 = (__nv_bfloat162*)g_ahi;
        __nv_bfloat162* alo2 = (__nv_bfloat162*)g_alo;
        const size_t rowbase = (size_t)(n * 16 + k2) * (CIN / 2);

        float v[2][2];
#pragma unroll
        for (int p = 0; p < 2; p++) {
            int c = p * 128 + ci * 2;
            v[p][0] = __ldg(&base[(size_t)c * SPOS]);
            v[p][1] = __ldg(&base[(size_t)(c + 1) * SPOS]);
        }
#pragma unroll 1
        for (int pass = 0; pass < 16; pass++) {
            const int pb = pass & 1;
            float u0 = v[pb][0], u1 = v[pb][1];
            if (pass + 2 < 16) {
                int c = (pass + 2) * 128 + ci * 2;
                v[pb][0] = __ldg(&base[(size_t)c * SPOS]);
                v[pb][1] = __ldg(&base[(size_t)(c + 1) * SPOS]);
            }
            __nv_bfloat16 h0 = __float2bfloat16_rn(u0);
            __nv_bfloat16 h1 = __float2bfloat16_rn(u1);
            __nv_bfloat16 l0 = __float2bfloat16_rn(u0 - __bfloat162float(h0));
            __nv_bfloat16 l1 = __float2bfloat16_rn(u1 - __bfloat162float(h1));
            smh[pb][ci][k] = __nv_bfloat162(h0, h1);
            sml[pb][ci][k] = __nv_bfloat162(l0, l1);
            __syncthreads();
            size_t o = rowbase + pass * 64 + c2;
            ahi2[o] = smh[pb][c2][k2];
            alo2[o] = sml[pb][c2][k2];
        }
    }
}

// ---------------- fused tail: GEMM1 + mix + FC-MMA + reduce (R10 structure) ----------------
__global__ void __launch_bounds__(256, 2)
k_tail(const float* __restrict__ conv_b,
       const float* __restrict__ fc_w,
       const float* __restrict__ fc_b,
       float* __restrict__ out) {
    extern __shared__ __align__(16) char smraw[];
    const int tid = threadIdx.x;
    const int blk = blockIdx.x;
    const int warp = tid >> 5, lane = tid & 31;

    __nv_bfloat16* Bsm = (__nv_bfloat16*)(smraw + SMB_OFF);
    __nv_bfloat16* Asm = (__nv_bfloat16*)(smraw + SMA_OFF);

    const int wm = warp & 1, wn = warp >> 1;   // 2 x 4 warp grid
    const int mrow0 = wm * 32;
    const int ncb = wn * 32;
    const int aRow = lane & 15, aCol = (lane >> 4) * 8;
    const int bRow = (lane & 7) + ((lane >> 4) & 1) * 8;
    const int bCol = ((lane >> 3) & 1) * 8;

    // ================= stage 1: GEMM1 (split-bf16 MMA, K-split 4) =================
    {
        const int mt = blk & 31;
        const int nt = (blk >> 5) & 1;
        const int ks = blk >> 6;
        const int m0 = mt * 64;
        const int ncol0 = nt * 128;
        const int kc0 = ks * 512;
        const int KITERS = 16;

        auto load_tile = [&](int t, int buf) {
            const int k0 = kc0 + t * KT;
            {
                int row = tid >> 2, kq = (tid & 3) * 8;
                cp16(&Asm[((buf * 2 + 0) * 64 + row) * APITCH + kq],
                     &g_ahi[(size_t)(m0 + row) * CIN + k0 + kq]);
                cp16(&Asm[((buf * 2 + 1) * 64 + row) * APITCH + kq],
                     &g_alo[(size_t)(m0 + row) * CIN + k0 + kq]);
            }
#pragma unroll
            for (int i = 0; i < 2; i++) {
                int q = tid + 256 * i;
                int col = q >> 2, kq = (q & 3) * 8;
                cp16(&Bsm[((buf * 2 + 0) * 128 + col) * BPITCH + kq],
                     &g_whi[(size_t)(ncol0 + col) * CIN + k0 + kq]);
                cp16(&Bsm[((buf * 2 + 1) * 128 + col) * BPITCH + kq],
                     &g_wlo[(size_t)(ncol0 + col) * CIN + k0 + kq]);
            }
        };

        float acc[2][4][4];
#pragma unroll
        for (int mi = 0; mi < 2; mi++)
#pragma unroll
            for (int nj = 0; nj < 4; nj++)
#pragma unroll
                for (int v = 0; v < 4; v++) acc[mi][nj][v] = 0.f;

        load_tile(0, 0);
        cp_commit();

        // ---- fc_w hi/lo split, hidden under the MMA pipeline (DRAM is idle here) ----
        {
            const float4* src = (const float4*)fc_w;
            __nv_bfloat162* dh = (__nv_bfloat162*)g_fwhi;
            __nv_bfloat162* dl = (__nv_bfloat162*)g_fwlo;
            int base = (blk * 256 + tid) * 8;   // float4 units; 524288 total
#pragma unroll
            for (int q = 0; q < 8; q++) {
                int i4 = base + q;
                float4 w4 = src[i4];
                float w[4] = {w4.x, w4.y, w4.z, w4.w};
                __nv_bfloat16 h[4], l[4];
#pragma unroll
                for (int j = 0; j < 4; j++) {
                    h[j] = __float2bfloat16_rn(w[j]);
                    l[j] = __float2bfloat16_rn(w[j] - __bfloat162float(h[j]));
                }
                dh[i4 * 2 + 0] = __nv_bfloat162(h[0], h[1]);
                dh[i4 * 2 + 1] = __nv_bfloat162(h[2], h[3]);
                dl[i4 * 2 + 0] = __nv_bfloat162(l[0], l[1]);
                dl[i4 * 2 + 1] = __nv_bfloat162(l[2], l[3]);
            }
        }

        for (int t = 0; t < KITERS; t++) {
            const int buf = t & 1;
            if (t + 1 < KITERS) {
                load_tile(t + 1, 1 - buf);
                cp_commit();
                cp_wait<1>();
            } else {
                cp_wait<0>();
            }
            __syncthreads();
            const __nv_bfloat16* Ah = Asm + (buf * 2 + 0) * 64 * APITCH;
            const __nv_bfloat16* Al = Asm + (buf * 2 + 1) * 64 * APITCH;
            const __nv_bfloat16* Bh = Bsm + (buf * 2 + 0) * 128 * BPITCH;
            const __nv_bfloat16* Bl = Bsm + (buf * 2 + 1) * 128 * BPITCH;
#pragma unroll
            for (int s16 = 0; s16 < KT; s16 += 16) {
                unsigned ah[2][4], al[2][4], bh[2][4], bl[2][4];
                ldsm_x4(ah[0], &Ah[(mrow0 + aRow) * APITCH + s16 + aCol]);
                ldsm_x4(ah[1], &Ah[(mrow0 + 16 + aRow) * APITCH + s16 + aCol]);
                ldsm_x4(al[0], &Al[(mrow0 + aRow) * APITCH + s16 + aCol]);
                ldsm_x4(al[1], &Al[(mrow0 + 16 + aRow) * APITCH + s16 + aCol]);
                ldsm_x4(bh[0], &Bh[(ncb + bRow) * BPITCH + s16 + bCol]);
                ldsm_x4(bh[1], &Bh[(ncb + 16 + bRow) * BPITCH + s16 + bCol]);
                ldsm_x4(bl[0], &Bl[(ncb + bRow) * BPITCH + s16 + bCol]);
                ldsm_x4(bl[1], &Bl[(ncb + 16 + bRow) * BPITCH + s16 + bCol]);
#pragma unroll
                for (int mi = 0; mi < 2; mi++) {
#pragma unroll
                    for (int nj = 0; nj < 4; nj++) {
                        const unsigned* bhf = &bh[nj >> 1][(nj & 1) * 2];
                        const unsigned* blf = &bl[nj >> 1][(nj & 1) * 2];
                        mma_bf16(acc[mi][nj], ah[mi], bhf);
                        mma_bf16(acc[mi][nj], ah[mi], blf);
                        mma_bf16(acc[mi][nj], al[mi], bhf);
                    }
                }
            }
            __syncthreads();
        }

        {
            int r = lane >> 2, cq = (lane & 3) * 2;
            float* dst = g_xpart[ks];
#pragma unroll
            for (int mi = 0; mi < 2; mi++) {
#pragma unroll
                for (int nj = 0; nj < 4; nj++) {
                    int row0 = m0 + mrow0 + mi * 16 + r;
                    int col = ncol0 + ncb + nj * 8 + cq;
                    *(float2*)&dst[(size_t)row0 * COUT + col] =
                        make_float2(acc[mi][nj][0], acc[mi][nj][1]);
                    *(float2*)&dst[(size_t)(row0 + 8) * COUT + col] =
                        make_float2(acc[mi][nj][2], acc[mi][nj][3]);
                }
            }
        }
    }

    gbar(0);

    // ================= stage 2: sum splits + bias + relu + lnorm mix -> y hi/lo =================
    if (blk < NBATCH) {
        float* L = (float*)smraw;
        const int n = blk;
        L[tid] = g_lnorm[n * 256 + tid];
        float b = conv_b[tid];
        float xv[16];
#pragma unroll
        for (int k = 0; k < 16; k++) {
            size_t idx = (size_t)(n * 16 + k) * COUT + tid;
            float s = g_xpart[0][idx] + g_xpart[1][idx] + g_xpart[2][idx] +
                      g_xpart[3][idx] + b;
            xv[k] = fmaxf(s, 0.f);
        }
        __syncthreads();
#pragma unroll
        for (int i = 0; i < 16; i++) {
            float y = 0.f;
#pragma unroll
            for (int j = 0; j < 16; j++) y += L[i * 16 + j] * xv[j];
            __nv_bfloat16 h = __float2bfloat16_rn(y);
            size_t o = (size_t)n * KFC + i * 256 + tid;
            g_yhi[o] = h;
            g_ylo[o] = __float2bfloat16_rn(y - __bfloat162float(h));
        }
    }

    gbar(1);

    // ================= stage 3: FC GEMM (split-bf16 MMA, K-split 32) =================
    {
        const int mt = blk & 1;
        const int nt = (blk >> 1) & 3;
        const int ks = blk >> 3;            // 0..31
        const int m0 = mt * 64;
        const int ncol0 = nt * 128;
        const int kc0 = ks * 128;
        const int KITERS = 4;

        auto load_tile = [&](int t, int buf) {
            const int k0 = kc0 + t * KT;
            {
                int row = tid >> 2, kq = (tid & 3) * 8;
                cp16(&Asm[((buf * 2 + 0) * 64 + row) * APITCH + kq],
                     &g_yhi[(size_t)(m0 + row) * KFC + k0 + kq]);
                cp16(&Asm[((buf * 2 + 1) * 64 + row) * APITCH + kq],
                     &g_ylo[(size_t)(m0 + row) * KFC + k0 + kq]);
            }
#pragma unroll
            for (int i = 0; i < 2; i++) {
                int q = tid + 256 * i;
                int col = q >> 2, kq = (q & 3) * 8;
                cp16(&Bsm[((buf * 2 + 0) * 128 + col) * BPITCH + kq],
                     &g_fwhi[(size_t)(ncol0 + col) * KFC + k0 + kq]);
                cp16(&Bsm[((buf * 2 + 1) * 128 + col) * BPITCH + kq],
                     &g_fwlo[(size_t)(ncol0 + col) * KFC + k0 + kq]);
            }
        };

        float acc[2][4][4];
#pragma unroll
        for (int mi = 0; mi < 2; mi++)
#pragma unroll
            for (int nj = 0; nj < 4; nj++)
#pragma unroll
                for (int v = 0; v < 4; v++) acc[mi][nj][v] = 0.f;

        load_tile(0, 0);
        cp_commit();

        for (int t = 0; t < KITERS; t++) {
            const int buf = t & 1;
            if (t + 1 < KITERS) {
                load_tile(t + 1, 1 - buf);
                cp_commit();
                cp_wait<1>();
            } else {
                cp_wait<0>();
            }
            __syncthreads();
            const __nv_bfloat16* Ah = Asm + (buf * 2 + 0) * 64 * APITCH;
            const __nv_bfloat16* Al = Asm + (buf * 2 + 1) * 64 * APITCH;
            const __nv_bfloat16* Bh = Bsm + (buf * 2 + 0) * 128 * BPITCH;
            const __nv_bfloat16* Bl = Bsm + (buf * 2 + 1) * 128 * BPITCH;
#pragma unroll
            for (int s16 = 0; s16 < KT; s16 += 16) {
                unsigned ah[2][4], al[2][4], bh[2][4], bl[2][4];
                ldsm_x4(ah[0], &Ah[(mrow0 + aRow) * APITCH + s16 + aCol]);
                ldsm_x4(ah[1], &Ah[(mrow0 + 16 + aRow) * APITCH + s16 + aCol]);
                ldsm_x4(al[0], &Al[(mrow0 + aRow) * APITCH + s16 + aCol]);
                ldsm_x4(al[1], &Al[(mrow0 + 16 + aRow) * APITCH + s16 + aCol]);
                ldsm_x4(bh[0], &Bh[(ncb + bRow) * BPITCH + s16 + bCol]);
                ldsm_x4(bh[1], &Bh[(ncb + 16 + bRow) * BPITCH + s16 + bCol]);
                ldsm_x4(bl[0], &Bl[(ncb + bRow) * BPITCH + s16 + bCol]);
                ldsm_x4(bl[1], &Bl[(ncb + 16 + bRow) * BPITCH + s16 + bCol]);
#pragma unroll
                for (int mi = 0; mi < 2; mi++) {
#pragma unroll
                    for (int nj = 0; nj < 4; nj++) {
                        const unsigned* bhf = &bh[nj >> 1][(nj & 1) * 2];
                        const unsigned* blf = &bl[nj >> 1][(nj & 1) * 2];
                        mma_bf16(acc[mi][nj], ah[mi], bhf);
                        mma_bf16(acc[mi][nj], ah[mi], blf);
                        mma_bf16(acc[mi][nj], al[mi], bhf);
                    }
                }
            }
            __syncthreads();
        }

        {
            int r = lane >> 2, cq = (lane & 3) * 2;
            float* dst = g_part2[ks];
#pragma unroll
            for (int mi = 0; mi < 2; mi++) {
#pragma unroll
                for (int nj = 0; nj < 4; nj++) {
                    int row0 = m0 + mrow0 + mi * 16 + r;
                    int col = ncol0 + ncb + nj * 8 + cq;
                    *(float2*)&dst[(size_t)row0 * DOUT + col] =
                        make_float2(acc[mi][nj][0], acc[mi][nj][1]);
                    *(float2*)&dst[(size_t)(row0 + 8) * DOUT + col] =
                        make_float2(acc[mi][nj][2], acc[mi][nj][3]);
                }
            }
        }
    }

    gbar(2);

    // ================= stage 4: reduce 32 k-splits + bias =================
    {
        int idx = blk * 256 + tid;      // 65536 = 128*512
        int d = idx & (DOUT - 1);
        float s = fc_b[d];
#pragma unroll
        for (int ks = 0; ks < FC_KSPLIT; ks++)
            s += g_part2[ks][idx];
        out[idx] = s;
    }
}

// ---------------- launch ----------------
extern "C" void kernel_launch(void* const* d_in, const int* in_sizes, int n_in,
                              void* d_out, int out_size) {
    const float* sounds = (const float*)d_in[0];
    const float* conv_w = (const float*)d_in[1];
    const float* conv_b = (const float*)d_in[2];
    const float* fc_w   = (const float*)d_in[3];
    const float* fc_b   = (const float*)d_in[4];
    float* out = (float*)d_out;

    cudaFuncSetAttribute(k_tail, cudaFuncAttributeMaxDynamicSharedMemorySize, SMEMSZ);

    k12_fused<<<128, 1024>>>(sounds, conv_w);
    k_tail<<<FUSED_BLOCKS, 256, SMEMSZ>>>(conv_b, fc_w, fc_b, out);
}

// round 13
// speedup vs baseline: 1.1398x; 1.1398x over previous
#include <cuda_runtime.h>
#include <cuda_bf16.h>
#include <cstdint>
#include <math.h>

#define NBATCH 128
#define CIN    2048
#define COUT   256
#define KNODES 16
#define SPOS   256
#define DOUT   512
#define KFC    4096
#define MROWS  2048
#define KSPLIT 4
#define FUSED_BLOCKS 256
#define FC_KSPLIT 32

// ---------------- device scratch ----------------
__device__ float g_lnorm[NBATCH * KNODES * KNODES];
__device__ __nv_bfloat16 g_whi[COUT * CIN];
__device__ __nv_bfloat16 g_wlo[COUT * CIN];
__device__ __nv_bfloat16 g_fwhi[DOUT * KFC];
__device__ __nv_bfloat16 g_fwlo[DOUT * KFC];
__device__ __nv_bfloat16 g_ahi[MROWS * CIN];
__device__ __nv_bfloat16 g_alo[MROWS * CIN];
__device__ __nv_bfloat16 g_yhi[NBATCH * KFC];
__device__ __nv_bfloat16 g_ylo[NBATCH * KFC];
__device__ float g_xpart[KSPLIT][MROWS * COUT];
__device__ float g_part2[FC_KSPLIT][NBATCH * DOUT];
__device__ volatile int g_bar[4];

// ---------------- async copy helpers ----------------
__device__ __forceinline__ void cp16(void* smem, const void* gmem) {
    unsigned int s = (unsigned int)__cvta_generic_to_shared(smem);
    asm volatile("cp.async.cg.shared.global [%0], [%1], 16;\n" :: "r"(s), "l"(gmem));
}
__device__ __forceinline__ void cp_commit() {
    asm volatile("cp.async.commit_group;\n" ::: "memory");
}
template <int N>
__device__ __forceinline__ void cp_wait() {
    asm volatile("cp.async.wait_group %0;\n" :: "n"(N) : "memory");
}

// ---------------- mma helpers ----------------
__device__ __forceinline__ void mma_bf16(float* c, const unsigned* a, const unsigned* b) {
    asm volatile(
        "mma.sync.aligned.m16n8k16.row.col.f32.bf16.bf16.f32 "
        "{%0,%1,%2,%3},{%4,%5,%6,%7},{%8,%9},{%0,%1,%2,%3};\n"
        : "+f"(c[0]), "+f"(c[1]), "+f"(c[2]), "+f"(c[3])
        : "r"(a[0]), "r"(a[1]), "r"(a[2]), "r"(a[3]), "r"(b[0]), "r"(b[1]));
}
__device__ __forceinline__ void ldsm_x4(unsigned* r, const void* p) {
    unsigned a = (unsigned)__cvta_generic_to_shared(p);
    asm volatile("ldmatrix.sync.aligned.m8n8.x4.shared.b16 {%0,%1,%2,%3}, [%4];\n"
                 : "=r"(r[0]), "=r"(r[1]), "=r"(r[2]), "=r"(r[3]) : "r"(a));
}

// ---------------- grid barrier ----------------
__device__ __forceinline__ void gbar(int id) {
    __syncthreads();
    __threadfence();
    if (threadIdx.x == 0) {
        atomicAdd((int*)&g_bar[id], 1);
        while (g_bar[id] < FUSED_BLOCKS) __nanosleep(64);
    }
    __syncthreads();
}

// ---------------- shared GEMM tile geometry ----------------
#define KT     32
#define APITCH 40
#define BPITCH 40
#define SMB_OFF 0
#define SMA_OFF (2 * 2 * 128 * BPITCH * 2)           // 40960
#define SMEMSZ  (SMA_OFF + 2 * 2 * 64 * APITCH * 2)  // 61440

// ---------------- K12: conv_w split + channel-sum + topk + lnorm + gather ----------------
// grid 128 (one block per n), 1024 threads.
__global__ void __launch_bounds__(1024, 1)
k12_fused(const float* __restrict__ sounds, const float* __restrict__ conv_w) {
    __shared__ float part[4][SPOS];
    __shared__ float feat[SPOS];
    __shared__ int   sel[KNODES];
    __shared__ int   rr[KNODES], cc[KNODES];
    __shared__ float Amat[KNODES][KNODES];
    __shared__ float dinv[KNODES];
    __shared__ int   spos[KNODES];
    __shared__ __nv_bfloat162 smh[2][64][17];
    __shared__ __nv_bfloat162 sml[2][64][17];

    const int n = blockIdx.x;
    const int tid = threadIdx.x;
    const float* snd_n = sounds + (size_t)n * CIN * SPOS;

    // ---- phase 0: barrier reset + conv_w hi/lo split ----
    if (n == 0 && tid < 4) g_bar[tid] = 0;
    {
        int i = (n * 1024 + tid) * 4;
        float4 w4 = *(const float4*)&conv_w[i];
        float w[4] = {w4.x, w4.y, w4.z, w4.w};
#pragma unroll
        for (int j = 0; j < 4; j++) {
            __nv_bfloat16 h = __float2bfloat16_rn(w[j]);
            g_whi[i + j] = h;
            g_wlo[i + j] = __float2bfloat16_rn(w[j] - __bfloat162float(h));
        }
    }

    // ---- phase A: channel sum ----
    {
        const int pos = tid & 255, cg = tid >> 8;
        const float* base = snd_n + (size_t)(cg * 512) * SPOS + pos;
        float a[8];
#pragma unroll
        for (int i = 0; i < 8; i++) a[i] = 0.f;
#pragma unroll 2
        for (int c = 0; c < 512; c += 8) {
#pragma unroll
            for (int i = 0; i < 8; i++) a[i] += base[(c + i) * SPOS];
        }
        part[cg][pos] =
            ((a[0] + a[1]) + (a[2] + a[3])) + ((a[4] + a[5]) + (a[6] + a[7]));
    }
    __syncthreads();
    if (tid < 256)
        feat[tid] = part[0][tid] + part[1][tid] + part[2][tid] + part[3][tid];
    __syncthreads();

    // ---- phase B: top-16 via single-warp register reduction ----
    if (tid < 32) {
        float vals[8];
#pragma unroll
        for (int j = 0; j < 8; j++) vals[j] = feat[tid * 8 + j];
#pragma unroll 1
        for (int it = 0; it < KNODES; it++) {
            unsigned long long k = 0ull;
#pragma unroll
            for (int j = 0; j < 8; j++) {
                unsigned fb = __float_as_uint(vals[j]);
                fb = (fb & 0x80000000u) ? ~fb : (fb | 0x80000000u);
                unsigned long long key =
                    ((unsigned long long)fb << 32) | (unsigned)(255 - (tid * 8 + j));
                if (key > k) k = key;
            }
#pragma unroll
            for (int s = 16; s > 0; s >>= 1) {
                unsigned long long o = __shfl_down_sync(0xffffffffu, k, s);
                if (o > k) k = o;
            }
            k = __shfl_sync(0xffffffffu, k, 0);
            int idx = 255 - (int)(k & 0xffffffffu);
            if (tid == (idx >> 3)) {
                int m = idx & 7;
#pragma unroll
                for (int j = 0; j < 8; j++)
                    if (j == m) vals[j] = -3.4e38f;
            }
            if (tid == 0) sel[it] = idx;
        }
    }
    __syncthreads();

    // ---- phase C: positions + lnorm ----
    if (tid < KNODES) {
        int p = sel[tid];
        int r = (p < 16) ? 0 : ((p >> 4) - 1);
        int q = p & 15;
        int c = (q == 0) ? 15 : (q - 1);
        rr[tid] = r;
        cc[tid] = c;
        spos[tid] = r * 16 + c;
    }
    __syncthreads();
    if (tid < 256) {
        int i = tid >> 4, j = tid & 15;
        float dr = (float)(rr[i] - rr[j]);
        float dc = (float)(cc[i] - cc[j]);
        Amat[i][j] = expf(-(dr * dr + dc * dc) / (2.0f * (float)KNODES));
    }
    __syncthreads();
    if (tid < KNODES) {
        float s = 0.f;
#pragma unroll
        for (int j = 0; j < KNODES; j++) s += Amat[tid][j];
        dinv[tid] = 1.0f / sqrtf(s);
    }
    __syncthreads();
    if (tid < 256) {
        int i = tid >> 4, j = tid & 15;
        g_lnorm[n * 256 + tid] = Amat[i][j] * dinv[i] * dinv[j];
    }

    // ---- phase D: gather + bf16 split + transpose (prefetch depth 2) ----
    {
        const int k = tid & 15, ci = (tid >> 4) & 63;
        const int k2 = tid >> 6, c2 = tid & 63;
        const float* base = snd_n + spos[k];
        __nv_bfloat162* ahi2 = (__nv_bfloat162*)g_ahi;
        __nv_bfloat162* alo2 = (__nv_bfloat162*)g_alo;
        const size_t rowbase = (size_t)(n * 16 + k2) * (CIN / 2);

        float v[2][2];
#pragma unroll
        for (int p = 0; p < 2; p++) {
            int c = p * 128 + ci * 2;
            v[p][0] = __ldg(&base[(size_t)c * SPOS]);
            v[p][1] = __ldg(&base[(size_t)(c + 1) * SPOS]);
        }
#pragma unroll 1
        for (int pass = 0; pass < 16; pass++) {
            const int pb = pass & 1;
            float u0 = v[pb][0], u1 = v[pb][1];
            if (pass + 2 < 16) {
                int c = (pass + 2) * 128 + ci * 2;
                v[pb][0] = __ldg(&base[(size_t)c * SPOS]);
                v[pb][1] = __ldg(&base[(size_t)(c + 1) * SPOS]);
            }
            __nv_bfloat16 h0 = __float2bfloat16_rn(u0);
            __nv_bfloat16 h1 = __float2bfloat16_rn(u1);
            __nv_bfloat16 l0 = __float2bfloat16_rn(u0 - __bfloat162float(h0));
            __nv_bfloat16 l1 = __float2bfloat16_rn(u1 - __bfloat162float(h1));
            smh[pb][ci][k] = __nv_bfloat162(h0, h1);
            sml[pb][ci][k] = __nv_bfloat162(l0, l1);
            __syncthreads();
            size_t o = rowbase + pass * 64 + c2;
            ahi2[o] = smh[pb][c2][k2];
            alo2[o] = sml[pb][c2][k2];
        }
    }
}

// ---------------- fused tail: GEMM1 + mix/fc-split + FC-MMA + reduce ----------------
__global__ void __launch_bounds__(256, 2)
k_tail(const float* __restrict__ conv_b,
       const float* __restrict__ fc_w,
       const float* __restrict__ fc_b,
       float* __restrict__ out) {
    extern __shared__ __align__(16) char smraw[];
    const int tid = threadIdx.x;
    const int blk = blockIdx.x;
    const int warp = tid >> 5, lane = tid & 31;

    __nv_bfloat16* Bsm = (__nv_bfloat16*)(smraw + SMB_OFF);
    __nv_bfloat16* Asm = (__nv_bfloat16*)(smraw + SMA_OFF);

    const int wm = warp & 1, wn = warp >> 1;   // 2 x 4 warp grid
    const int mrow0 = wm * 32;
    const int ncb = wn * 32;
    const int aRow = lane & 15, aCol = (lane >> 4) * 8;
    const int bRow = (lane & 7) + ((lane >> 4) & 1) * 8;
    const int bCol = ((lane >> 3) & 1) * 8;

    // ================= stage 1: GEMM1 (split-bf16 MMA, K-split 4) =================
    {
        const int mt = blk & 31;
        const int nt = (blk >> 5) & 1;
        const int ks = blk >> 6;
        const int m0 = mt * 64;
        const int ncol0 = nt * 128;
        const int kc0 = ks * 512;
        const int KITERS = 16;

        auto load_tile = [&](int t, int buf) {
            const int k0 = kc0 + t * KT;
            {
                int row = tid >> 2, kq = (tid & 3) * 8;
                cp16(&Asm[((buf * 2 + 0) * 64 + row) * APITCH + kq],
                     &g_ahi[(size_t)(m0 + row) * CIN + k0 + kq]);
                cp16(&Asm[((buf * 2 + 1) * 64 + row) * APITCH + kq],
                     &g_alo[(size_t)(m0 + row) * CIN + k0 + kq]);
            }
#pragma unroll
            for (int i = 0; i < 2; i++) {
                int q = tid + 256 * i;
                int col = q >> 2, kq = (q & 3) * 8;
                cp16(&Bsm[((buf * 2 + 0) * 128 + col) * BPITCH + kq],
                     &g_whi[(size_t)(ncol0 + col) * CIN + k0 + kq]);
                cp16(&Bsm[((buf * 2 + 1) * 128 + col) * BPITCH + kq],
                     &g_wlo[(size_t)(ncol0 + col) * CIN + k0 + kq]);
            }
        };

        float acc[2][4][4];
#pragma unroll
        for (int mi = 0; mi < 2; mi++)
#pragma unroll
            for (int nj = 0; nj < 4; nj++)
#pragma unroll
                for (int v = 0; v < 4; v++) acc[mi][nj][v] = 0.f;

        load_tile(0, 0);
        cp_commit();

        for (int t = 0; t < KITERS; t++) {
            const int buf = t & 1;
            if (t + 1 < KITERS) {
                load_tile(t + 1, 1 - buf);
                cp_commit();
                cp_wait<1>();
            } else {
                cp_wait<0>();
            }
            __syncthreads();
            const __nv_bfloat16* Ah = Asm + (buf * 2 + 0) * 64 * APITCH;
            const __nv_bfloat16* Al = Asm + (buf * 2 + 1) * 64 * APITCH;
            const __nv_bfloat16* Bh = Bsm + (buf * 2 + 0) * 128 * BPITCH;
            const __nv_bfloat16* Bl = Bsm + (buf * 2 + 1) * 128 * BPITCH;
#pragma unroll
            for (int s16 = 0; s16 < KT; s16 += 16) {
                unsigned ah[2][4], al[2][4], bh[2][4], bl[2][4];
                ldsm_x4(ah[0], &Ah[(mrow0 + aRow) * APITCH + s16 + aCol]);
                ldsm_x4(ah[1], &Ah[(mrow0 + 16 + aRow) * APITCH + s16 + aCol]);
                ldsm_x4(al[0], &Al[(mrow0 + aRow) * APITCH + s16 + aCol]);
                ldsm_x4(al[1], &Al[(mrow0 + 16 + aRow) * APITCH + s16 + aCol]);
                ldsm_x4(bh[0], &Bh[(ncb + bRow) * BPITCH + s16 + bCol]);
                ldsm_x4(bh[1], &Bh[(ncb + 16 + bRow) * BPITCH + s16 + bCol]);
                ldsm_x4(bl[0], &Bl[(ncb + bRow) * BPITCH + s16 + bCol]);
                ldsm_x4(bl[1], &Bl[(ncb + 16 + bRow) * BPITCH + s16 + bCol]);
#pragma unroll
                for (int mi = 0; mi < 2; mi++) {
#pragma unroll
                    for (int nj = 0; nj < 4; nj++) {
                        const unsigned* bhf = &bh[nj >> 1][(nj & 1) * 2];
                        const unsigned* blf = &bl[nj >> 1][(nj & 1) * 2];
                        mma_bf16(acc[mi][nj], ah[mi], bhf);
                        mma_bf16(acc[mi][nj], ah[mi], blf);
                        mma_bf16(acc[mi][nj], al[mi], bhf);
                    }
                }
            }
            __syncthreads();
        }

        {
            int r = lane >> 2, cq = (lane & 3) * 2;
            float* dst = g_xpart[ks];
#pragma unroll
            for (int mi = 0; mi < 2; mi++) {
#pragma unroll
                for (int nj = 0; nj < 4; nj++) {
                    int row0 = m0 + mrow0 + mi * 16 + r;
                    int col = ncol0 + ncb + nj * 8 + cq;
                    *(float2*)&dst[(size_t)row0 * COUT + col] =
                        make_float2(acc[mi][nj][0], acc[mi][nj][1]);
                    *(float2*)&dst[(size_t)(row0 + 8) * COUT + col] =
                        make_float2(acc[mi][nj][2], acc[mi][nj][3]);
                }
            }
        }
    }

    gbar(0);

    // ====== stage 2: blocks 0..127: mix -> y hi/lo; blocks 128..255: fc_w split ======
    if (blk < NBATCH) {
        float* L = (float*)smraw;
        const int n = blk;
        L[tid] = g_lnorm[n * 256 + tid];
        float b = conv_b[tid];
        float xv[16];
#pragma unroll
        for (int k = 0; k < 16; k++) {
            size_t idx = (size_t)(n * 16 + k) * COUT + tid;
            float s = g_xpart[0][idx] + g_xpart[1][idx] + g_xpart[2][idx] +
                      g_xpart[3][idx] + b;
            xv[k] = fmaxf(s, 0.f);
        }
        __syncthreads();
#pragma unroll
        for (int i = 0; i < 16; i++) {
            float y = 0.f;
#pragma unroll
            for (int j = 0; j < 16; j++) y += L[i * 16 + j] * xv[j];
            __nv_bfloat16 h = __float2bfloat16_rn(y);
            size_t o = (size_t)n * KFC + i * 256 + tid;
            g_yhi[o] = h;
            g_ylo[o] = __float2bfloat16_rn(y - __bfloat162float(h));
        }
    } else {
        // fc_w hi/lo split by the 128 otherwise-idle blocks (DRAM idle here;
        // register scope fully isolated from the MMA loops)
        const float4* src = (const float4*)fc_w;
        __nv_bfloat162* dh = (__nv_bfloat162*)g_fwhi;
        __nv_bfloat162* dl = (__nv_bfloat162*)g_fwlo;
        int base = ((blk - NBATCH) * 256 + tid) * 16;   // float4 units; 524288 total
#pragma unroll 4
        for (int q = 0; q < 16; q++) {
            int i4 = base + q;
            float4 w4 = src[i4];
            float w[4] = {w4.x, w4.y, w4.z, w4.w};
            __nv_bfloat16 h[4], l[4];
#pragma unroll
            for (int j = 0; j < 4; j++) {
                h[j] = __float2bfloat16_rn(w[j]);
                l[j] = __float2bfloat16_rn(w[j] - __bfloat162float(h[j]));
            }
            dh[i4 * 2 + 0] = __nv_bfloat162(h[0], h[1]);
            dh[i4 * 2 + 1] = __nv_bfloat162(h[2], h[3]);
            dl[i4 * 2 + 0] = __nv_bfloat162(l[0], l[1]);
            dl[i4 * 2 + 1] = __nv_bfloat162(l[2], l[3]);
        }
    }

    gbar(1);

    // ================= stage 3: FC GEMM (split-bf16 MMA, K-split 32) =================
    {
        const int mt = blk & 1;
        const int nt = (blk >> 1) & 3;
        const int ks = blk >> 3;            // 0..31
        const int m0 = mt * 64;
        const int ncol0 = nt * 128;
        const int kc0 = ks * 128;
        const int KITERS = 4;

        auto load_tile = [&](int t, int buf) {
            const int k0 = kc0 + t * KT;
            {
                int row = tid >> 2, kq = (tid & 3) * 8;
                cp16(&Asm[((buf * 2 + 0) * 64 + row) * APITCH + kq],
                     &g_yhi[(size_t)(m0 + row) * KFC + k0 + kq]);
                cp16(&Asm[((buf * 2 + 1) * 64 + row) * APITCH + kq],
                     &g_ylo[(size_t)(m0 + row) * KFC + k0 + kq]);
            }
#pragma unroll
            for (int i = 0; i < 2; i++) {
                int q = tid + 256 * i;
                int col = q >> 2, kq = (q & 3) * 8;
                cp16(&Bsm[((buf * 2 + 0) * 128 + col) * BPITCH + kq],
                     &g_fwhi[(size_t)(ncol0 + col) * KFC + k0 + kq]);
                cp16(&Bsm[((buf * 2 + 1) * 128 + col) * BPITCH + kq],
                     &g_fwlo[(size_t)(ncol0 + col) * KFC + k0 + kq]);
            }
        };

        float acc[2][4][4];
#pragma unroll
        for (int mi = 0; mi < 2; mi++)
#pragma unroll
            for (int nj = 0; nj < 4; nj++)
#pragma unroll
                for (int v = 0; v < 4; v++) acc[mi][nj][v] = 0.f;

        load_tile(0, 0);
        cp_commit();

        for (int t = 0; t < KITERS; t++) {
            const int buf = t & 1;
            if (t + 1 < KITERS) {
                load_tile(t + 1, 1 - buf);
                cp_commit();
                cp_wait<1>();
            } else {
                cp_wait<0>();
            }
            __syncthreads();
            const __nv_bfloat16* Ah = Asm + (buf * 2 + 0) * 64 * APITCH;
            const __nv_bfloat16* Al = Asm + (buf * 2 + 1) * 64 * APITCH;
            const __nv_bfloat16* Bh = Bsm + (buf * 2 + 0) * 128 * BPITCH;
            const __nv_bfloat16* Bl = Bsm + (buf * 2 + 1) * 128 * BPITCH;
#pragma unroll
            for (int s16 = 0; s16 < KT; s16 += 16) {
                unsigned ah[2][4], al[2][4], bh[2][4], bl[2][4];
                ldsm_x4(ah[0], &Ah[(mrow0 + aRow) * APITCH + s16 + aCol]);
                ldsm_x4(ah[1], &Ah[(mrow0 + 16 + aRow) * APITCH + s16 + aCol]);
                ldsm_x4(al[0], &Al[(mrow0 + aRow) * APITCH + s16 + aCol]);
                ldsm_x4(al[1], &Al[(mrow0 + 16 + aRow) * APITCH + s16 + aCol]);
                ldsm_x4(bh[0], &Bh[(ncb + bRow) * BPITCH + s16 + bCol]);
                ldsm_x4(bh[1], &Bh[(ncb + 16 + bRow) * BPITCH + s16 + bCol]);
                ldsm_x4(bl[0], &Bl[(ncb + bRow) * BPITCH + s16 + bCol]);
                ldsm_x4(bl[1], &Bl[(ncb + 16 + bRow) * BPITCH + s16 + bCol]);
#pragma unroll
                for (int mi = 0; mi < 2; mi++) {
#pragma unroll
                    for (int nj = 0; nj < 4; nj++) {
                        const unsigned* bhf = &bh[nj >> 1][(nj & 1) * 2];
                        const unsigned* blf = &bl[nj >> 1][(nj & 1) * 2];
                        mma_bf16(acc[mi][nj], ah[mi], bhf);
                        mma_bf16(acc[mi][nj], ah[mi], blf);
                        mma_bf16(acc[mi][nj], al[mi], bhf);
                    }
                }
            }
            __syncthreads();
        }

        {
            int r = lane >> 2, cq = (lane & 3) * 2;
            float* dst = g_part2[ks];
#pragma unroll
            for (int mi = 0; mi < 2; mi++) {
#pragma unroll
                for (int nj = 0; nj < 4; nj++) {
                    int row0 = m0 + mrow0 + mi * 16 + r;
                    int col = ncol0 + ncb + nj * 8 + cq;
                    *(float2*)&dst[(size_t)row0 * DOUT + col] =
                        make_float2(acc[mi][nj][0], acc[mi][nj][1]);
                    *(float2*)&dst[(size_t)(row0 + 8) * DOUT + col] =
                        make_float2(acc[mi][nj][2], acc[mi][nj][3]);
                }
            }
        }
    }

    gbar(2);

    // ================= stage 4: reduce 32 k-splits + bias =================
    {
        int idx = blk * 256 + tid;      // 65536 = 128*512
        int d = idx & (DOUT - 1);
        float s = fc_b[d];
#pragma unroll
        for (int ks = 0; ks < FC_KSPLIT; ks++)
            s += g_part2[ks][idx];
        out[idx] = s;
    }
}

// ---------------- launch ----------------
extern "C" void kernel_launch(void* const* d_in, const int* in_sizes, int n_in,
                              void* d_out, int out_size) {
    const float* sounds = (const float*)d_in[0];
    const float* conv_w = (const float*)d_in[1];
    const float* conv_b = (const float*)d_in[2];
    const float* fc_w   = (const float*)d_in[3];
    const float* fc_b   = (const float*)d_in[4];
    float* out = (float*)d_out;

    cudaFuncSetAttribute(k_tail, cudaFuncAttributeMaxDynamicSharedMemorySize, SMEMSZ);

    k12_fused<<<128, 1024>>>(sounds, conv_w);
    k_tail<<<FUSED_BLOCKS, 256, SMEMSZ>>>(conv_b, fc_w, fc_b, out);
}

// round 14
// speedup vs baseline: 1.3061x; 1.1459x over previous
#include <cuda_runtime.h>
#include <cuda_bf16.h>
#include <cstdint>
#include <math.h>

#define NBATCH 128
#define CIN    2048
#define COUT   256
#define KNODES 16
#define SPOS   256
#define DOUT   512
#define KFC    4096
#define MROWS  2048
#define KSPLIT 4
#define FUSED_BLOCKS 256
#define FC_KSPLIT 32

// ---------------- device scratch ----------------
__device__ float g_lnorm[NBATCH * KNODES * KNODES];
__device__ __nv_bfloat16 g_whi[COUT * CIN];
__device__ __nv_bfloat16 g_wlo[COUT * CIN];
__device__ __nv_bfloat16 g_fwhi[DOUT * KFC];
__device__ __nv_bfloat16 g_fwlo[DOUT * KFC];
__device__ __nv_bfloat16 g_ahi[MROWS * CIN];
__device__ __nv_bfloat16 g_alo[MROWS * CIN];
__device__ __nv_bfloat16 g_yhi[NBATCH * KFC];
__device__ __nv_bfloat16 g_ylo[NBATCH * KFC];
__device__ float g_xpart[KSPLIT][MROWS * COUT];
__device__ float g_part2[FC_KSPLIT][NBATCH * DOUT];
__device__ volatile int g_bar[4];

// ---------------- async copy helpers ----------------
__device__ __forceinline__ void cp16(void* smem, const void* gmem) {
    unsigned int s = (unsigned int)__cvta_generic_to_shared(smem);
    asm volatile("cp.async.cg.shared.global [%0], [%1], 16;\n" :: "r"(s), "l"(gmem));
}
__device__ __forceinline__ void cp_commit() {
    asm volatile("cp.async.commit_group;\n" ::: "memory");
}
template <int N>
__device__ __forceinline__ void cp_wait() {
    asm volatile("cp.async.wait_group %0;\n" :: "n"(N) : "memory");
}

// ---------------- mma helpers ----------------
__device__ __forceinline__ void mma_bf16(float* c, const unsigned* a, const unsigned* b) {
    asm volatile(
        "mma.sync.aligned.m16n8k16.row.col.f32.bf16.bf16.f32 "
        "{%0,%1,%2,%3},{%4,%5,%6,%7},{%8,%9},{%0,%1,%2,%3};\n"
        : "+f"(c[0]), "+f"(c[1]), "+f"(c[2]), "+f"(c[3])
        : "r"(a[0]), "r"(a[1]), "r"(a[2]), "r"(a[3]), "r"(b[0]), "r"(b[1]));
}
__device__ __forceinline__ void ldsm_x4(unsigned* r, const void* p) {
    unsigned a = (unsigned)__cvta_generic_to_shared(p);
    asm volatile("ldmatrix.sync.aligned.m8n8.x4.shared.b16 {%0,%1,%2,%3}, [%4];\n"
                 : "=r"(r[0]), "=r"(r[1]), "=r"(r[2]), "=r"(r[3]) : "r"(a));
}

// ---------------- grid barrier ----------------
__device__ __forceinline__ void gbar(int id) {
    __syncthreads();
    __threadfence();
    if (threadIdx.x == 0) {
        atomicAdd((int*)&g_bar[id], 1);
        while (g_bar[id] < FUSED_BLOCKS) __nanosleep(64);
    }
    __syncthreads();
}

// ---------------- shared GEMM tile geometry ----------------
#define KT     32
#define APITCH 40
#define BPITCH 40
#define SMB_OFF 0
#define SMA_OFF (2 * 2 * 128 * BPITCH * 2)           // 40960
#define SMEMSZ  (SMA_OFF + 2 * 2 * 64 * APITCH * 2)  // 61440

// ---------------- K12: conv_w split + channel-sum + topk + lnorm + gather ----------------
// grid 128 (one block per n), 1024 threads.
__global__ void __launch_bounds__(1024, 1)
k12_fused(const float* __restrict__ sounds, const float* __restrict__ conv_w) {
    __shared__ float part[4][SPOS];
    __shared__ float feat[SPOS];
    __shared__ int   sel[KNODES];
    __shared__ int   rr[KNODES], cc[KNODES];
    __shared__ float Amat[KNODES][KNODES];
    __shared__ float dinv[KNODES];
    __shared__ int   spos[KNODES];
    __shared__ __nv_bfloat162 smh[2][64][17];
    __shared__ __nv_bfloat162 sml[2][64][17];

    const int n = blockIdx.x;
    const int tid = threadIdx.x;
    const float* snd_n = sounds + (size_t)n * CIN * SPOS;

    // ---- phase 0: barrier reset + conv_w hi/lo split (coalesced: lane stride 16B) ----
    if (n == 0 && tid < 4) g_bar[tid] = 0;
    {
        int i = (n * 1024 + tid) * 4;
        float4 w4 = *(const float4*)&conv_w[i];
        float w[4] = {w4.x, w4.y, w4.z, w4.w};
#pragma unroll
        for (int j = 0; j < 4; j++) {
            __nv_bfloat16 h = __float2bfloat16_rn(w[j]);
            g_whi[i + j] = h;
            g_wlo[i + j] = __float2bfloat16_rn(w[j] - __bfloat162float(h));
        }
    }

    // ---- phase A: channel sum ----
    {
        const int pos = tid & 255, cg = tid >> 8;
        const float* base = snd_n + (size_t)(cg * 512) * SPOS + pos;
        float a[8];
#pragma unroll
        for (int i = 0; i < 8; i++) a[i] = 0.f;
#pragma unroll 2
        for (int c = 0; c < 512; c += 8) {
#pragma unroll
            for (int i = 0; i < 8; i++) a[i] += base[(c + i) * SPOS];
        }
        part[cg][pos] =
            ((a[0] + a[1]) + (a[2] + a[3])) + ((a[4] + a[5]) + (a[6] + a[7]));
    }
    __syncthreads();
    if (tid < 256)
        feat[tid] = part[0][tid] + part[1][tid] + part[2][tid] + part[3][tid];
    __syncthreads();

    // ---- phase B: top-16 via single-warp register reduction ----
    if (tid < 32) {
        float vals[8];
#pragma unroll
        for (int j = 0; j < 8; j++) vals[j] = feat[tid * 8 + j];
#pragma unroll 1
        for (int it = 0; it < KNODES; it++) {
            unsigned long long k = 0ull;
#pragma unroll
            for (int j = 0; j < 8; j++) {
                unsigned fb = __float_as_uint(vals[j]);
                fb = (fb & 0x80000000u) ? ~fb : (fb | 0x80000000u);
                unsigned long long key =
                    ((unsigned long long)fb << 32) | (unsigned)(255 - (tid * 8 + j));
                if (key > k) k = key;
            }
#pragma unroll
            for (int s = 16; s > 0; s >>= 1) {
                unsigned long long o = __shfl_down_sync(0xffffffffu, k, s);
                if (o > k) k = o;
            }
            k = __shfl_sync(0xffffffffu, k, 0);
            int idx = 255 - (int)(k & 0xffffffffu);
            if (tid == (idx >> 3)) {
                int m = idx & 7;
#pragma unroll
                for (int j = 0; j < 8; j++)
                    if (j == m) vals[j] = -3.4e38f;
            }
            if (tid == 0) sel[it] = idx;
        }
    }
    __syncthreads();

    // ---- phase C: positions + lnorm ----
    if (tid < KNODES) {
        int p = sel[tid];
        int r = (p < 16) ? 0 : ((p >> 4) - 1);
        int q = p & 15;
        int c = (q == 0) ? 15 : (q - 1);
        rr[tid] = r;
        cc[tid] = c;
        spos[tid] = r * 16 + c;
    }
    __syncthreads();
    if (tid < 256) {
        int i = tid >> 4, j = tid & 15;
        float dr = (float)(rr[i] - rr[j]);
        float dc = (float)(cc[i] - cc[j]);
        Amat[i][j] = expf(-(dr * dr + dc * dc) / (2.0f * (float)KNODES));
    }
    __syncthreads();
    if (tid < KNODES) {
        float s = 0.f;
#pragma unroll
        for (int j = 0; j < KNODES; j++) s += Amat[tid][j];
        dinv[tid] = 1.0f / sqrtf(s);
    }
    __syncthreads();
    if (tid < 256) {
        int i = tid >> 4, j = tid & 15;
        g_lnorm[n * 256 + tid] = Amat[i][j] * dinv[i] * dinv[j];
    }

    // ---- phase D: gather + bf16 split + transpose (prefetch depth 2) ----
    {
        const int k = tid & 15, ci = (tid >> 4) & 63;
        const int k2 = tid >> 6, c2 = tid & 63;
        const float* base = snd_n + spos[k];
        __nv_bfloat162* ahi2 = (__nv_bfloat162*)g_ahi;
        __nv_bfloat162* alo2 = (__nv_bfloat162*)g_alo;
        const size_t rowbase = (size_t)(n * 16 + k2) * (CIN / 2);

        float v[2][2];
#pragma unroll
        for (int p = 0; p < 2; p++) {
            int c = p * 128 + ci * 2;
            v[p][0] = __ldg(&base[(size_t)c * SPOS]);
            v[p][1] = __ldg(&base[(size_t)(c + 1) * SPOS]);
        }
#pragma unroll 1
        for (int pass = 0; pass < 16; pass++) {
            const int pb = pass & 1;
            float u0 = v[pb][0], u1 = v[pb][1];
            if (pass + 2 < 16) {
                int c = (pass + 2) * 128 + ci * 2;
                v[pb][0] = __ldg(&base[(size_t)c * SPOS]);
                v[pb][1] = __ldg(&base[(size_t)(c + 1) * SPOS]);
            }
            __nv_bfloat16 h0 = __float2bfloat16_rn(u0);
            __nv_bfloat16 h1 = __float2bfloat16_rn(u1);
            __nv_bfloat16 l0 = __float2bfloat16_rn(u0 - __bfloat162float(h0));
            __nv_bfloat16 l1 = __float2bfloat16_rn(u1 - __bfloat162float(h1));
            smh[pb][ci][k] = __nv_bfloat162(h0, h1);
            sml[pb][ci][k] = __nv_bfloat162(l0, l1);
            __syncthreads();
            size_t o = rowbase + pass * 64 + c2;
            ahi2[o] = smh[pb][c2][k2];
            alo2[o] = sml[pb][c2][k2];
        }
    }
}

// ---------------- fused tail: GEMM1 + mix/fc-split + FC-MMA + reduce ----------------
__global__ void __launch_bounds__(256, 2)
k_tail(const float* __restrict__ conv_b,
       const float* __restrict__ fc_w,
       const float* __restrict__ fc_b,
       float* __restrict__ out) {
    extern __shared__ __align__(16) char smraw[];
    const int tid = threadIdx.x;
    const int blk = blockIdx.x;
    const int warp = tid >> 5, lane = tid & 31;

    __nv_bfloat16* Bsm = (__nv_bfloat16*)(smraw + SMB_OFF);
    __nv_bfloat16* Asm = (__nv_bfloat16*)(smraw + SMA_OFF);

    const int wm = warp & 1, wn = warp >> 1;   // 2 x 4 warp grid
    const int mrow0 = wm * 32;
    const int ncb = wn * 32;
    const int aRow = lane & 15, aCol = (lane >> 4) * 8;
    const int bRow = (lane & 7) + ((lane >> 4) & 1) * 8;
    const int bCol = ((lane >> 3) & 1) * 8;

    // ================= stage 1: GEMM1 (split-bf16 MMA, K-split 4) =================
    {
        const int mt = blk & 31;
        const int nt = (blk >> 5) & 1;
        const int ks = blk >> 6;
        const int m0 = mt * 64;
        const int ncol0 = nt * 128;
        const int kc0 = ks * 512;
        const int KITERS = 16;

        auto load_tile = [&](int t, int buf) {
            const int k0 = kc0 + t * KT;
            {
                int row = tid >> 2, kq = (tid & 3) * 8;
                cp16(&Asm[((buf * 2 + 0) * 64 + row) * APITCH + kq],
                     &g_ahi[(size_t)(m0 + row) * CIN + k0 + kq]);
                cp16(&Asm[((buf * 2 + 1) * 64 + row) * APITCH + kq],
                     &g_alo[(size_t)(m0 + row) * CIN + k0 + kq]);
            }
#pragma unroll
            for (int i = 0; i < 2; i++) {
                int q = tid + 256 * i;
                int col = q >> 2, kq = (q & 3) * 8;
                cp16(&Bsm[((buf * 2 + 0) * 128 + col) * BPITCH + kq],
                     &g_whi[(size_t)(ncol0 + col) * CIN + k0 + kq]);
                cp16(&Bsm[((buf * 2 + 1) * 128 + col) * BPITCH + kq],
                     &g_wlo[(size_t)(ncol0 + col) * CIN + k0 + kq]);
            }
        };

        float acc[2][4][4];
#pragma unroll
        for (int mi = 0; mi < 2; mi++)
#pragma unroll
            for (int nj = 0; nj < 4; nj++)
#pragma unroll
                for (int v = 0; v < 4; v++) acc[mi][nj][v] = 0.f;

        load_tile(0, 0);
        cp_commit();

        for (int t = 0; t < KITERS; t++) {
            const int buf = t & 1;
            if (t + 1 < KITERS) {
                load_tile(t + 1, 1 - buf);
                cp_commit();
                cp_wait<1>();
            } else {
                cp_wait<0>();
            }
            __syncthreads();
            const __nv_bfloat16* Ah = Asm + (buf * 2 + 0) * 64 * APITCH;
            const __nv_bfloat16* Al = Asm + (buf * 2 + 1) * 64 * APITCH;
            const __nv_bfloat16* Bh = Bsm + (buf * 2 + 0) * 128 * BPITCH;
            const __nv_bfloat16* Bl = Bsm + (buf * 2 + 1) * 128 * BPITCH;
#pragma unroll
            for (int s16 = 0; s16 < KT; s16 += 16) {
                unsigned ah[2][4], al[2][4], bh[2][4], bl[2][4];
                ldsm_x4(ah[0], &Ah[(mrow0 + aRow) * APITCH + s16 + aCol]);
                ldsm_x4(ah[1], &Ah[(mrow0 + 16 + aRow) * APITCH + s16 + aCol]);
                ldsm_x4(al[0], &Al[(mrow0 + aRow) * APITCH + s16 + aCol]);
                ldsm_x4(al[1], &Al[(mrow0 + 16 + aRow) * APITCH + s16 + aCol]);
                ldsm_x4(bh[0], &Bh[(ncb + bRow) * BPITCH + s16 + bCol]);
                ldsm_x4(bh[1], &Bh[(ncb + 16 + bRow) * BPITCH + s16 + bCol]);
                ldsm_x4(bl[0], &Bl[(ncb + bRow) * BPITCH + s16 + bCol]);
                ldsm_x4(bl[1], &Bl[(ncb + 16 + bRow) * BPITCH + s16 + bCol]);
#pragma unroll
                for (int mi = 0; mi < 2; mi++) {
#pragma unroll
                    for (int nj = 0; nj < 4; nj++) {
                        const unsigned* bhf = &bh[nj >> 1][(nj & 1) * 2];
                        const unsigned* blf = &bl[nj >> 1][(nj & 1) * 2];
                        mma_bf16(acc[mi][nj], ah[mi], bhf);
                        mma_bf16(acc[mi][nj], ah[mi], blf);
                        mma_bf16(acc[mi][nj], al[mi], bhf);
                    }
                }
            }
            __syncthreads();
        }

        {
            int r = lane >> 2, cq = (lane & 3) * 2;
            float* dst = g_xpart[ks];
#pragma unroll
            for (int mi = 0; mi < 2; mi++) {
#pragma unroll
                for (int nj = 0; nj < 4; nj++) {
                    int row0 = m0 + mrow0 + mi * 16 + r;
                    int col = ncol0 + ncb + nj * 8 + cq;
                    *(float2*)&dst[(size_t)row0 * COUT + col] =
                        make_float2(acc[mi][nj][0], acc[mi][nj][1]);
                    *(float2*)&dst[(size_t)(row0 + 8) * COUT + col] =
                        make_float2(acc[mi][nj][2], acc[mi][nj][3]);
                }
            }
        }
    }

    gbar(0);

    // ====== stage 2: blocks 0..127: mix -> y hi/lo; blocks 128..255: fc_w split ======
    if (blk < NBATCH) {
        float* L = (float*)smraw;
        const int n = blk;
        L[tid] = g_lnorm[n * 256 + tid];
        float b = conv_b[tid];
        float xv[16];
#pragma unroll
        for (int k = 0; k < 16; k++) {
            size_t idx = (size_t)(n * 16 + k) * COUT + tid;
            float s = g_xpart[0][idx] + g_xpart[1][idx] + g_xpart[2][idx] +
                      g_xpart[3][idx] + b;
            xv[k] = fmaxf(s, 0.f);
        }
        __syncthreads();
#pragma unroll
        for (int i = 0; i < 16; i++) {
            float y = 0.f;
#pragma unroll
            for (int j = 0; j < 16; j++) y += L[i * 16 + j] * xv[j];
            __nv_bfloat16 h = __float2bfloat16_rn(y);
            size_t o = (size_t)n * KFC + i * 256 + tid;
            g_yhi[o] = h;
            g_ylo[o] = __float2bfloat16_rn(y - __bfloat162float(h));
        }
    } else {
        // fc_w hi/lo split by the 128 otherwise-idle blocks.
        // COALESCED: grid-stride over float4s — adjacent lanes -> adjacent 16B.
        const float4* src = (const float4*)fc_w;
        __nv_bfloat162* dh = (__nv_bfloat162*)g_fwhi;
        __nv_bfloat162* dl = (__nv_bfloat162*)g_fwlo;
        const int gtid = (blk - NBATCH) * 256 + tid;   // 0..32767
#pragma unroll 4
        for (int q = 0; q < 16; q++) {
            int i4 = q * 32768 + gtid;                 // 524288 total float4
            float4 w4 = src[i4];
            float w[4] = {w4.x, w4.y, w4.z, w4.w};
            __nv_bfloat16 h[4], l[4];
#pragma unroll
            for (int j = 0; j < 4; j++) {
                h[j] = __float2bfloat16_rn(w[j]);
                l[j] = __float2bfloat16_rn(w[j] - __bfloat162float(h[j]));
            }
            dh[i4 * 2 + 0] = __nv_bfloat162(h[0], h[1]);
            dh[i4 * 2 + 1] = __nv_bfloat162(h[2], h[3]);
            dl[i4 * 2 + 0] = __nv_bfloat162(l[0], l[1]);
            dl[i4 * 2 + 1] = __nv_bfloat162(l[2], l[3]);
        }
    }

    gbar(1);

    // ================= stage 3: FC GEMM (split-bf16 MMA, K-split 32) =================
    {
        const int mt = blk & 1;
        const int nt = (blk >> 1) & 3;
        const int ks = blk >> 3;            // 0..31
        const int m0 = mt * 64;
        const int ncol0 = nt * 128;
        const int kc0 = ks * 128;
        const int KITERS = 4;

        auto load_tile = [&](int t, int buf) {
            const int k0 = kc0 + t * KT;
            {
                int row = tid >> 2, kq = (tid & 3) * 8;
                cp16(&Asm[((buf * 2 + 0) * 64 + row) * APITCH + kq],
                     &g_yhi[(size_t)(m0 + row) * KFC + k0 + kq]);
                cp16(&Asm[((buf * 2 + 1) * 64 + row) * APITCH + kq],
                     &g_ylo[(size_t)(m0 + row) * KFC + k0 + kq]);
            }
#pragma unroll
            for (int i = 0; i < 2; i++) {
                int q = tid + 256 * i;
                int col = q >> 2, kq = (q & 3) * 8;
                cp16(&Bsm[((buf * 2 + 0) * 128 + col) * BPITCH + kq],
                     &g_fwhi[(size_t)(ncol0 + col) * KFC + k0 + kq]);
                cp16(&Bsm[((buf * 2 + 1) * 128 + col) * BPITCH + kq],
                     &g_fwlo[(size_t)(ncol0 + col) * KFC + k0 + kq]);
            }
        };

        float acc[2][4][4];
#pragma unroll
        for (int mi = 0; mi < 2; mi++)
#pragma unroll
            for (int nj = 0; nj < 4; nj++)
#pragma unroll
                for (int v = 0; v < 4; v++) acc[mi][nj][v] = 0.f;

        load_tile(0, 0);
        cp_commit();

        for (int t = 0; t < KITERS; t++) {
            const int buf = t & 1;
            if (t + 1 < KITERS) {
                load_tile(t + 1, 1 - buf);
                cp_commit();
                cp_wait<1>();
            } else {
                cp_wait<0>();
            }
            __syncthreads();
            const __nv_bfloat16* Ah = Asm + (buf * 2 + 0) * 64 * APITCH;
            const __nv_bfloat16* Al = Asm + (buf * 2 + 1) * 64 * APITCH;
            const __nv_bfloat16* Bh = Bsm + (buf * 2 + 0) * 128 * BPITCH;
            const __nv_bfloat16* Bl = Bsm + (buf * 2 + 1) * 128 * BPITCH;
#pragma unroll
            for (int s16 = 0; s16 < KT; s16 += 16) {
                unsigned ah[2][4], al[2][4], bh[2][4], bl[2][4];
                ldsm_x4(ah[0], &Ah[(mrow0 + aRow) * APITCH + s16 + aCol]);
                ldsm_x4(ah[1], &Ah[(mrow0 + 16 + aRow) * APITCH + s16 + aCol]);
                ldsm_x4(al[0], &Al[(mrow0 + aRow) * APITCH + s16 + aCol]);
                ldsm_x4(al[1], &Al[(mrow0 + 16 + aRow) * APITCH + s16 + aCol]);
                ldsm_x4(bh[0], &Bh[(ncb + bRow) * BPITCH + s16 + bCol]);
                ldsm_x4(bh[1], &Bh[(ncb + 16 + bRow) * BPITCH + s16 + bCol]);
                ldsm_x4(bl[0], &Bl[(ncb + bRow) * BPITCH + s16 + bCol]);
                ldsm_x4(bl[1], &Bl[(ncb + 16 + bRow) * BPITCH + s16 + bCol]);
#pragma unroll
                for (int mi = 0; mi < 2; mi++) {
#pragma unroll
                    for (int nj = 0; nj < 4; nj++) {
                        const unsigned* bhf = &bh[nj >> 1][(nj & 1) * 2];
                        const unsigned* blf = &bl[nj >> 1][(nj & 1) * 2];
                        mma_bf16(acc[mi][nj], ah[mi], bhf);
                        mma_bf16(acc[mi][nj], ah[mi], blf);
                        mma_bf16(acc[mi][nj], al[mi], bhf);
                    }
                }
            }
            __syncthreads();
        }

        {
            int r = lane >> 2, cq = (lane & 3) * 2;
            float* dst = g_part2[ks];
#pragma unroll
            for (int mi = 0; mi < 2; mi++) {
#pragma unroll
                for (int nj = 0; nj < 4; nj++) {
                    int row0 = m0 + mrow0 + mi * 16 + r;
                    int col = ncol0 + ncb + nj * 8 + cq;
                    *(float2*)&dst[(size_t)row0 * DOUT + col] =
                        make_float2(acc[mi][nj][0], acc[mi][nj][1]);
                    *(float2*)&dst[(size_t)(row0 + 8) * DOUT + col] =
                        make_float2(acc[mi][nj][2], acc[mi][nj][3]);
                }
            }
        }
    }

    gbar(2);

    // ================= stage 4: reduce 32 k-splits + bias =================
    {
        int idx = blk * 256 + tid;      // 65536 = 128*512
        int d = idx & (DOUT - 1);
        float s = fc_b[d];
#pragma unroll
        for (int ks = 0; ks < FC_KSPLIT; ks++)
            s += g_part2[ks][idx];
        out[idx] = s;
    }
}

// ---------------- launch ----------------
extern "C" void kernel_launch(void* const* d_in, const int* in_sizes, int n_in,
                              void* d_out, int out_size) {
    const float* sounds = (const float*)d_in[0];
    const float* conv_w = (const float*)d_in[1];
    const float* conv_b = (const float*)d_in[2];
    const float* fc_w   = (const float*)d_in[3];
    const float* fc_b   = (const float*)d_in[4];
    float* out = (float*)d_out;

    cudaFuncSetAttribute(k_tail, cudaFuncAttributeMaxDynamicSharedMemorySize, SMEMSZ);

    k12_fused<<<128, 1024>>>(sounds, conv_w);
    k_tail<<<FUSED_BLOCKS, 256, SMEMSZ>>>(conv_b, fc_w, fc_b, out);
}

// round 15
// speedup vs baseline: 1.3185x; 1.0095x over previous
#include <cuda_runtime.h>
#include <cuda_bf16.h>
#include <cstdint>
#include <math.h>

#define NBATCH 128
#define CIN    2048
#define COUT   256
#define KNODES 16
#define SPOS   256
#define DOUT   512
#define KFC    4096
#define MROWS  2048
#define KSPLIT 4
#define FUSED_BLOCKS 256
#define FC_KSPLIT 32

// ---------------- device scratch ----------------
__device__ float g_lnorm[NBATCH * KNODES * KNODES];
__device__ __nv_bfloat16 g_whi[COUT * CIN];
__device__ __nv_bfloat16 g_wlo[COUT * CIN];
__device__ __nv_bfloat16 g_fwhi[DOUT * KFC];
__device__ __nv_bfloat16 g_fwlo[DOUT * KFC];
__device__ __nv_bfloat16 g_ahi[MROWS * CIN];
__device__ __nv_bfloat16 g_alo[MROWS * CIN];
__device__ __nv_bfloat16 g_yhi[NBATCH * KFC];
__device__ __nv_bfloat16 g_ylo[NBATCH * KFC];
__device__ float g_xpart[KSPLIT][MROWS * COUT];
__device__ float g_part2[FC_KSPLIT][NBATCH * DOUT];
__device__ volatile int g_bar[4];

// ---------------- async copy helpers ----------------
__device__ __forceinline__ void cp16(void* smem, const void* gmem) {
    unsigned int s = (unsigned int)__cvta_generic_to_shared(smem);
    asm volatile("cp.async.cg.shared.global [%0], [%1], 16;\n" :: "r"(s), "l"(gmem));
}
__device__ __forceinline__ void cp_commit() {
    asm volatile("cp.async.commit_group;\n" ::: "memory");
}
template <int N>
__device__ __forceinline__ void cp_wait() {
    asm volatile("cp.async.wait_group %0;\n" :: "n"(N) : "memory");
}

// ---------------- mma helpers ----------------
__device__ __forceinline__ void mma_bf16(float* c, const unsigned* a, const unsigned* b) {
    asm volatile(
        "mma.sync.aligned.m16n8k16.row.col.f32.bf16.bf16.f32 "
        "{%0,%1,%2,%3},{%4,%5,%6,%7},{%8,%9},{%0,%1,%2,%3};\n"
        : "+f"(c[0]), "+f"(c[1]), "+f"(c[2]), "+f"(c[3])
        : "r"(a[0]), "r"(a[1]), "r"(a[2]), "r"(a[3]), "r"(b[0]), "r"(b[1]));
}
__device__ __forceinline__ void ldsm_x4(unsigned* r, const void* p) {
    unsigned a = (unsigned)__cvta_generic_to_shared(p);
    asm volatile("ldmatrix.sync.aligned.m8n8.x4.shared.b16 {%0,%1,%2,%3}, [%4];\n"
                 : "=r"(r[0]), "=r"(r[1]), "=r"(r[2]), "=r"(r[3]) : "r"(a));
}

// ---------------- grid barrier ----------------
__device__ __forceinline__ void gbar(int id) {
    __syncthreads();
    __threadfence();
    if (threadIdx.x == 0) {
        atomicAdd((int*)&g_bar[id], 1);
        while (g_bar[id] < FUSED_BLOCKS) __nanosleep(64);
    }
    __syncthreads();
}

// ---------------- GEMM tile geometry (3-stage, single-sync pipeline) ----------------
#define KT      32
#define APITCH  40
#define BPITCH  40
#define STAGE_B (2 * 128 * BPITCH * 2)     // 20480
#define STAGE_A (2 * 64 * APITCH * 2)      // 10240
#define STAGE_SZ (STAGE_B + STAGE_A)       // 30720
#define SMEMSZ  (3 * STAGE_SZ)             // 92160

// ---------------- K12: conv_w split + channel-sum + topk + lnorm + gather ----------------
// grid 128 (one block per n), 1024 threads.  (unchanged from R14)
__global__ void __launch_bounds__(1024, 1)
k12_fused(const float* __restrict__ sounds, const float* __restrict__ conv_w) {
    __shared__ float part[4][SPOS];
    __shared__ float feat[SPOS];
    __shared__ int   sel[KNODES];
    __shared__ int   rr[KNODES], cc[KNODES];
    __shared__ float Amat[KNODES][KNODES];
    __shared__ float dinv[KNODES];
    __shared__ int   spos[KNODES];
    __shared__ __nv_bfloat162 smh[2][64][17];
    __shared__ __nv_bfloat162 sml[2][64][17];

    const int n = blockIdx.x;
    const int tid = threadIdx.x;
    const float* snd_n = sounds + (size_t)n * CIN * SPOS;

    if (n == 0 && tid < 4) g_bar[tid] = 0;
    {
        int i = (n * 1024 + tid) * 4;
        float4 w4 = *(const float4*)&conv_w[i];
        float w[4] = {w4.x, w4.y, w4.z, w4.w};
#pragma unroll
        for (int j = 0; j < 4; j++) {
            __nv_bfloat16 h = __float2bfloat16_rn(w[j]);
            g_whi[i + j] = h;
            g_wlo[i + j] = __float2bfloat16_rn(w[j] - __bfloat162float(h));
        }
    }

    {
        const int pos = tid & 255, cg = tid >> 8;
        const float* base = snd_n + (size_t)(cg * 512) * SPOS + pos;
        float a[8];
#pragma unroll
        for (int i = 0; i < 8; i++) a[i] = 0.f;
#pragma unroll 2
        for (int c = 0; c < 512; c += 8) {
#pragma unroll
            for (int i = 0; i < 8; i++) a[i] += base[(c + i) * SPOS];
        }
        part[cg][pos] =
            ((a[0] + a[1]) + (a[2] + a[3])) + ((a[4] + a[5]) + (a[6] + a[7]));
    }
    __syncthreads();
    if (tid < 256)
        feat[tid] = part[0][tid] + part[1][tid] + part[2][tid] + part[3][tid];
    __syncthreads();

    if (tid < 32) {
        float vals[8];
#pragma unroll
        for (int j = 0; j < 8; j++) vals[j] = feat[tid * 8 + j];
#pragma unroll 1
        for (int it = 0; it < KNODES; it++) {
            unsigned long long k = 0ull;
#pragma unroll
            for (int j = 0; j < 8; j++) {
                unsigned fb = __float_as_uint(vals[j]);
                fb = (fb & 0x80000000u) ? ~fb : (fb | 0x80000000u);
                unsigned long long key =
                    ((unsigned long long)fb << 32) | (unsigned)(255 - (tid * 8 + j));
                if (key > k) k = key;
            }
#pragma unroll
            for (int s = 16; s > 0; s >>= 1) {
                unsigned long long o = __shfl_down_sync(0xffffffffu, k, s);
                if (o > k) k = o;
            }
            k = __shfl_sync(0xffffffffu, k, 0);
            int idx = 255 - (int)(k & 0xffffffffu);
            if (tid == (idx >> 3)) {
                int m = idx & 7;
#pragma unroll
                for (int j = 0; j < 8; j++)
                    if (j == m) vals[j] = -3.4e38f;
            }
            if (tid == 0) sel[it] = idx;
        }
    }
    __syncthreads();

    if (tid < KNODES) {
        int p = sel[tid];
        int r = (p < 16) ? 0 : ((p >> 4) - 1);
        int q = p & 15;
        int c = (q == 0) ? 15 : (q - 1);
        rr[tid] = r;
        cc[tid] = c;
        spos[tid] = r * 16 + c;
    }
    __syncthreads();
    if (tid < 256) {
        int i = tid >> 4, j = tid & 15;
        float dr = (float)(rr[i] - rr[j]);
        float dc = (float)(cc[i] - cc[j]);
        Amat[i][j] = expf(-(dr * dr + dc * dc) / (2.0f * (float)KNODES));
    }
    __syncthreads();
    if (tid < KNODES) {
        float s = 0.f;
#pragma unroll
        for (int j = 0; j < KNODES; j++) s += Amat[tid][j];
        dinv[tid] = 1.0f / sqrtf(s);
    }
    __syncthreads();
    if (tid < 256) {
        int i = tid >> 4, j = tid & 15;
        g_lnorm[n * 256 + tid] = Amat[i][j] * dinv[i] * dinv[j];
    }

    {
        const int k = tid & 15, ci = (tid >> 4) & 63;
        const int k2 = tid >> 6, c2 = tid & 63;
        const float* base = snd_n + spos[k];
        __nv_bfloat162* ahi2 = (__nv_bfloat162*)g_ahi;
        __nv_bfloat162* alo2 = (__nv_bfloat162*)g_alo;
        const size_t rowbase = (size_t)(n * 16 + k2) * (CIN / 2);

        float v[2][2];
#pragma unroll
        for (int p = 0; p < 2; p++) {
            int c = p * 128 + ci * 2;
            v[p][0] = __ldg(&base[(size_t)c * SPOS]);
            v[p][1] = __ldg(&base[(size_t)(c + 1) * SPOS]);
        }
#pragma unroll 1
        for (int pass = 0; pass < 16; pass++) {
            const int pb = pass & 1;
            float u0 = v[pb][0], u1 = v[pb][1];
            if (pass + 2 < 16) {
                int c = (pass + 2) * 128 + ci * 2;
                v[pb][0] = __ldg(&base[(size_t)c * SPOS]);
                v[pb][1] = __ldg(&base[(size_t)(c + 1) * SPOS]);
            }
            __nv_bfloat16 h0 = __float2bfloat16_rn(u0);
            __nv_bfloat16 h1 = __float2bfloat16_rn(u1);
            __nv_bfloat16 l0 = __float2bfloat16_rn(u0 - __bfloat162float(h0));
            __nv_bfloat16 l1 = __float2bfloat16_rn(u1 - __bfloat162float(h1));
            smh[pb][ci][k] = __nv_bfloat162(h0, h1);
            sml[pb][ci][k] = __nv_bfloat162(l0, l1);
            __syncthreads();
            size_t o = rowbase + pass * 64 + c2;
            ahi2[o] = smh[pb][c2][k2];
            alo2[o] = sml[pb][c2][k2];
        }
    }
}

// ---------------- fused tail: GEMM1 + mix/fc-split + FC-MMA + reduce ----------------
__global__ void __launch_bounds__(256, 2)
k_tail(const float* __restrict__ conv_b,
       const float* __restrict__ fc_w,
       const float* __restrict__ fc_b,
       float* __restrict__ out) {
    extern __shared__ __align__(16) char smraw[];
    const int tid = threadIdx.x;
    const int blk = blockIdx.x;
    const int warp = tid >> 5, lane = tid & 31;

    const int wm = warp & 1, wn = warp >> 1;   // 2 x 4 warp grid
    const int mrow0 = wm * 32;
    const int ncb = wn * 32;
    const int aRow = lane & 15, aCol = (lane >> 4) * 8;
    const int bRow = (lane & 7) + ((lane >> 4) & 1) * 8;
    const int bCol = ((lane >> 3) & 1) * 8;

    // ================= stage 1: GEMM1 (split-bf16 MMA, K-split 4) =================
    {
        const int mt = blk & 31;
        const int nt = (blk >> 5) & 1;
        const int ks = blk >> 6;
        const int m0 = mt * 64;
        const int ncol0 = nt * 128;
        const int kc0 = ks * 512;
        const int KITERS = 16;

        auto load_tile = [&](int t, int s) {
            __nv_bfloat16* Bs = (__nv_bfloat16*)(smraw + s * STAGE_SZ);
            __nv_bfloat16* As = (__nv_bfloat16*)(smraw + s * STAGE_SZ + STAGE_B);
            const int k0 = kc0 + t * KT;
            {
                int row = tid >> 2, kq = (tid & 3) * 8;
                cp16(&As[(0 * 64 + row) * APITCH + kq],
                     &g_ahi[(size_t)(m0 + row) * CIN + k0 + kq]);
                cp16(&As[(1 * 64 + row) * APITCH + kq],
                     &g_alo[(size_t)(m0 + row) * CIN + k0 + kq]);
            }
#pragma unroll
            for (int i = 0; i < 2; i++) {
                int q = tid + 256 * i;
                int col = q >> 2, kq = (q & 3) * 8;
                cp16(&Bs[(0 * 128 + col) * BPITCH + kq],
                     &g_whi[(size_t)(ncol0 + col) * CIN + k0 + kq]);
                cp16(&Bs[(1 * 128 + col) * BPITCH + kq],
                     &g_wlo[(size_t)(ncol0 + col) * CIN + k0 + kq]);
            }
        };

        float acc[2][4][4];
#pragma unroll
        for (int mi = 0; mi < 2; mi++)
#pragma unroll
            for (int nj = 0; nj < 4; nj++)
#pragma unroll
                for (int v = 0; v < 4; v++) acc[mi][nj][v] = 0.f;

        load_tile(0, 0);
        cp_commit();
        load_tile(1, 1);
        cp_commit();

        for (int t = 0; t < KITERS; t++) {
            const int s = t % 3;
            if (t + 1 < KITERS) cp_wait<1>();   // tile t landed; t+1 in flight
            else                cp_wait<0>();
            __syncthreads();                    // all warps done with buffer (t+2)%3's old data
            if (t + 2 < KITERS) {
                load_tile(t + 2, (t + 2) % 3);
                cp_commit();
            }
            const __nv_bfloat16* Bh = (__nv_bfloat16*)(smraw + s * STAGE_SZ);
            const __nv_bfloat16* Bl = Bh + 128 * BPITCH;
            const __nv_bfloat16* Ah = (__nv_bfloat16*)(smraw + s * STAGE_SZ + STAGE_B);
            const __nv_bfloat16* Al = Ah + 64 * APITCH;
#pragma unroll
            for (int s16 = 0; s16 < KT; s16 += 16) {
                unsigned ah[2][4], al[2][4], bh[2][4], bl[2][4];
                ldsm_x4(ah[0], &Ah[(mrow0 + aRow) * APITCH + s16 + aCol]);
                ldsm_x4(ah[1], &Ah[(mrow0 + 16 + aRow) * APITCH + s16 + aCol]);
                ldsm_x4(al[0], &Al[(mrow0 + aRow) * APITCH + s16 + aCol]);
                ldsm_x4(al[1], &Al[(mrow0 + 16 + aRow) * APITCH + s16 + aCol]);
                ldsm_x4(bh[0], &Bh[(ncb + bRow) * BPITCH + s16 + bCol]);
                ldsm_x4(bh[1], &Bh[(ncb + 16 + bRow) * BPITCH + s16 + bCol]);
                ldsm_x4(bl[0], &Bl[(ncb + bRow) * BPITCH + s16 + bCol]);
                ldsm_x4(bl[1], &Bl[(ncb + 16 + bRow) * BPITCH + s16 + bCol]);
#pragma unroll
                for (int mi = 0; mi < 2; mi++) {
#pragma unroll
                    for (int nj = 0; nj < 4; nj++) {
                        const unsigned* bhf = &bh[nj >> 1][(nj & 1) * 2];
                        const unsigned* blf = &bl[nj >> 1][(nj & 1) * 2];
                        mma_bf16(acc[mi][nj], ah[mi], bhf);
                        mma_bf16(acc[mi][nj], ah[mi], blf);
                        mma_bf16(acc[mi][nj], al[mi], bhf);
                    }
                }
            }
        }

        {
            int r = lane >> 2, cq = (lane & 3) * 2;
            float* dst = g_xpart[ks];
#pragma unroll
            for (int mi = 0; mi < 2; mi++) {
#pragma unroll
                for (int nj = 0; nj < 4; nj++) {
                    int row0 = m0 + mrow0 + mi * 16 + r;
                    int col = ncol0 + ncb + nj * 8 + cq;
                    *(float2*)&dst[(size_t)row0 * COUT + col] =
                        make_float2(acc[mi][nj][0], acc[mi][nj][1]);
                    *(float2*)&dst[(size_t)(row0 + 8) * COUT + col] =
                        make_float2(acc[mi][nj][2], acc[mi][nj][3]);
                }
            }
        }
    }

    gbar(0);

    // ====== stage 2: blocks 0..127: mix -> y hi/lo; blocks 128..255: fc_w split ======
    if (blk < NBATCH) {
        float* L = (float*)smraw;
        const int n = blk;
        L[tid] = g_lnorm[n * 256 + tid];
        float b = conv_b[tid];
        float xv[16];
#pragma unroll
        for (int k = 0; k < 16; k++) {
            size_t idx = (size_t)(n * 16 + k) * COUT + tid;
            float s = g_xpart[0][idx] + g_xpart[1][idx] + g_xpart[2][idx] +
                      g_xpart[3][idx] + b;
            xv[k] = fmaxf(s, 0.f);
        }
        __syncthreads();
#pragma unroll
        for (int i = 0; i < 16; i++) {
            float y = 0.f;
#pragma unroll
            for (int j = 0; j < 16; j++) y += L[i * 16 + j] * xv[j];
            __nv_bfloat16 h = __float2bfloat16_rn(y);
            size_t o = (size_t)n * KFC + i * 256 + tid;
            g_yhi[o] = h;
            g_ylo[o] = __float2bfloat16_rn(y - __bfloat162float(h));
        }
    } else {
        // fc_w hi/lo split — COALESCED grid-stride over float4s
        const float4* src = (const float4*)fc_w;
        __nv_bfloat162* dh = (__nv_bfloat162*)g_fwhi;
        __nv_bfloat162* dl = (__nv_bfloat162*)g_fwlo;
        const int gtid = (blk - NBATCH) * 256 + tid;   // 0..32767
#pragma unroll 4
        for (int q = 0; q < 16; q++) {
            int i4 = q * 32768 + gtid;                 // 524288 total float4
            float4 w4 = src[i4];
            float w[4] = {w4.x, w4.y, w4.z, w4.w};
            __nv_bfloat16 h[4], l[4];
#pragma unroll
            for (int j = 0; j < 4; j++) {
                h[j] = __float2bfloat16_rn(w[j]);
                l[j] = __float2bfloat16_rn(w[j] - __bfloat162float(h[j]));
            }
            dh[i4 * 2 + 0] = __nv_bfloat162(h[0], h[1]);
            dh[i4 * 2 + 1] = __nv_bfloat162(h[2], h[3]);
            dl[i4 * 2 + 0] = __nv_bfloat162(l[0], l[1]);
            dl[i4 * 2 + 1] = __nv_bfloat162(l[2], l[3]);
        }
    }

    gbar(1);

    // ================= stage 3: FC GEMM (split-bf16 MMA, K-split 32) =================
    {
        const int mt = blk & 1;
        const int nt = (blk >> 1) & 3;
        const int ks = blk >> 3;            // 0..31
        const int m0 = mt * 64;
        const int ncol0 = nt * 128;
        const int kc0 = ks * 128;
        const int KITERS = 4;

        auto load_tile = [&](int t, int s) {
            __nv_bfloat16* Bs = (__nv_bfloat16*)(smraw + s * STAGE_SZ);
            __nv_bfloat16* As = (__nv_bfloat16*)(smraw + s * STAGE_SZ + STAGE_B);
            const int k0 = kc0 + t * KT;
            {
                int row = tid >> 2, kq = (tid & 3) * 8;
                cp16(&As[(0 * 64 + row) * APITCH + kq],
                     &g_yhi[(size_t)(m0 + row) * KFC + k0 + kq]);
                cp16(&As[(1 * 64 + row) * APITCH + kq],
                     &g_ylo[(size_t)(m0 + row) * KFC + k0 + kq]);
            }
#pragma unroll
            for (int i = 0; i < 2; i++) {
                int q = tid + 256 * i;
                int col = q >> 2, kq = (q & 3) * 8;
                cp16(&Bs[(0 * 128 + col) * BPITCH + kq],
                     &g_fwhi[(size_t)(ncol0 + col) * KFC + k0 + kq]);
                cp16(&Bs[(1 * 128 + col) * BPITCH + kq],
                     &g_fwlo[(size_t)(ncol0 + col) * KFC + k0 + kq]);
            }
        };

        float acc[2][4][4];
#pragma unroll
        for (int mi = 0; mi < 2; mi++)
#pragma unroll
            for (int nj = 0; nj < 4; nj++)
#pragma unroll
                for (int v = 0; v < 4; v++) acc[mi][nj][v] = 0.f;

        load_tile(0, 0);
        cp_commit();
        load_tile(1, 1);
        cp_commit();

        for (int t = 0; t < KITERS; t++) {
            const int s = t % 3;
            if (t + 1 < KITERS) cp_wait<1>();
            else                cp_wait<0>();
            __syncthreads();
            if (t + 2 < KITERS) {
                load_tile(t + 2, (t + 2) % 3);
                cp_commit();
            }
            const __nv_bfloat16* Bh = (__nv_bfloat16*)(smraw + s * STAGE_SZ);
            const __nv_bfloat16* Bl = Bh + 128 * BPITCH;
            const __nv_bfloat16* Ah = (__nv_bfloat16*)(smraw + s * STAGE_SZ + STAGE_B);
            const __nv_bfloat16* Al = Ah + 64 * APITCH;
#pragma unroll
            for (int s16 = 0; s16 < KT; s16 += 16) {
                unsigned ah[2][4], al[2][4], bh[2][4], bl[2][4];
                ldsm_x4(ah[0], &Ah[(mrow0 + aRow) * APITCH + s16 + aCol]);
                ldsm_x4(ah[1], &Ah[(mrow0 + 16 + aRow) * APITCH + s16 + aCol]);
                ldsm_x4(al[0], &Al[(mrow0 + aRow) * APITCH + s16 + aCol]);
                ldsm_x4(al[1], &Al[(mrow0 + 16 + aRow) * APITCH + s16 + aCol]);
                ldsm_x4(bh[0], &Bh[(ncb + bRow) * BPITCH + s16 + bCol]);
                ldsm_x4(bh[1], &Bh[(ncb + 16 + bRow) * BPITCH + s16 + bCol]);
                ldsm_x4(bl[0], &Bl[(ncb + bRow) * BPITCH + s16 + bCol]);
                ldsm_x4(bl[1], &Bl[(ncb + 16 + bRow) * BPITCH + s16 + bCol]);
#pragma unroll
                for (int mi = 0; mi < 2; mi++) {
#pragma unroll
                    for (int nj = 0; nj < 4; nj++) {
                        const unsigned* bhf = &bh[nj >> 1][(nj & 1) * 2];
                        const unsigned* blf = &bl[nj >> 1][(nj & 1) * 2];
                        mma_bf16(acc[mi][nj], ah[mi], bhf);
                        mma_bf16(acc[mi][nj], ah[mi], blf);
                        mma_bf16(acc[mi][nj], al[mi], bhf);
                    }
                }
            }
        }

        {
            int r = lane >> 2, cq = (lane & 3) * 2;
            float* dst = g_part2[ks];
#pragma unroll
            for (int mi = 0; mi < 2; mi++) {
#pragma unroll
                for (int nj = 0; nj < 4; nj++) {
                    int row0 = m0 + mrow0 + mi * 16 + r;
                    int col = ncol0 + ncb + nj * 8 + cq;
                    *(float2*)&dst[(size_t)row0 * DOUT + col] =
                        make_float2(acc[mi][nj][0], acc[mi][nj][1]);
                    *(float2*)&dst[(size_t)(row0 + 8) * DOUT + col] =
                        make_float2(acc[mi][nj][2], acc[mi][nj][3]);
                }
            }
        }
    }

    gbar(2);

    // ================= stage 4: reduce 32 k-splits + bias =================
    {
        int idx = blk * 256 + tid;      // 65536 = 128*512
        int d = idx & (DOUT - 1);
        float s = fc_b[d];
#pragma unroll
        for (int ks = 0; ks < FC_KSPLIT; ks++)
            s += g_part2[ks][idx];
        out[idx] = s;
    }
}

// ---------------- launch ----------------
extern "C" void kernel_launch(void* const* d_in, const int* in_sizes, int n_in,
                              void* d_out, int out_size) {
    const float* sounds = (const float*)d_in[0];
    const float* conv_w = (const float*)d_in[1];
    const float* conv_b = (const float*)d_in[2];
    const float* fc_w   = (const float*)d_in[3];
    const float* fc_b   = (const float*)d_in[4];
    float* out = (float*)d_out;

    cudaFuncSetAttribute(k_tail, cudaFuncAttributeMaxDynamicSharedMemorySize, SMEMSZ);

    k12_fused<<<128, 1024>>>(sounds, conv_w);
    k_tail<<<FUSED_BLOCKS, 256, SMEMSZ>>>(conv_b, fc_w, fc_b, out);
}